// round 4
// baseline (speedup 1.0000x reference)
#include <cuda_runtime.h>
#include <math.h>

#define BATCH  16
#define CH     256
#define NSP    1024      // H*W = 32*32
#define NHEADS 4
#define HD     64        // head dim
#define NGRP   32
#define CPG    8         // channels per group

// Scratch (allocation-free: __device__ globals)
__device__ float g_h  [BATCH * CH * NSP];        // 16 MB  groupnorm output
__device__ float g_qkv[BATCH * 3 * CH * NSP];    // 48 MB  qkv projections
__device__ float g_att[BATCH * CH * NSP];        // 16 MB  attention output

// ---------------------------------------------------------------------------
// GroupNorm: one block per (batch, group). Group = 8 channels x 1024 = 8192
// contiguous floats. Two-pass (mean/var reduce, then normalize).
// ---------------------------------------------------------------------------
__global__ void __launch_bounds__(256)
gn_kernel(const float* __restrict__ x,
          const float* __restrict__ gamma,
          const float* __restrict__ beta) {
    int b = blockIdx.x >> 5;
    int g = blockIdx.x & 31;
    const float4* xb = (const float4*)(x + ((size_t)b * CH + g * CPG) * NSP);
    float4*       hb = (float4*)(g_h + ((size_t)b * CH + g * CPG) * NSP);

    float s = 0.f, s2 = 0.f;
    for (int i = threadIdx.x; i < 2048; i += 256) {
        float4 v = xb[i];
        s  += v.x + v.y + v.z + v.w;
        s2 += v.x * v.x + v.y * v.y + v.z * v.z + v.w * v.w;
    }
    __shared__ float rs[256], rq[256];
    rs[threadIdx.x] = s; rq[threadIdx.x] = s2;
    __syncthreads();
    for (int o = 128; o > 0; o >>= 1) {
        if (threadIdx.x < o) {
            rs[threadIdx.x] += rs[threadIdx.x + o];
            rq[threadIdx.x] += rq[threadIdx.x + o];
        }
        __syncthreads();
    }
    __shared__ float mu_s, rstd_s;
    if (threadIdx.x == 0) {
        float mu  = rs[0] * (1.f / 8192.f);
        float var = rq[0] * (1.f / 8192.f) - mu * mu;
        mu_s = mu;
        rstd_s = rsqrtf(var + 1e-5f);
    }
    __syncthreads();
    float mu = mu_s, rstd = rstd_s;
    for (int i = threadIdx.x; i < 2048; i += 256) {
        int c = g * CPG + (i >> 8);              // (i*4)/1024
        float ga = gamma[c] * rstd;
        float be = beta[c] - mu * ga;
        float4 v = xb[i];
        v.x = v.x * ga + be; v.y = v.y * ga + be;
        v.z = v.z * ga + be; v.w = v.w * ga + be;
        hb[i] = v;
    }
}

// ---------------------------------------------------------------------------
// Channel GEMM: out[b,m,n] = sum_k W[m,k] * inp[b,k,n] (+bias, +residual).
// 64x64 output tile, K chunks of 16. 16x16 threads, each a 4x4 micro-tile
// with strided ownership (rows ty+16r, cols tx+16c) -> conflict-free LDS.
// ---------------------------------------------------------------------------
template<int MOUT, bool QKV_MODE>
__global__ void __launch_bounds__(256)
gemm_kernel(const float* __restrict__ W, const float* __restrict__ bias,
            const float* __restrict__ resid, float* __restrict__ outp) {
    const float* inp = QKV_MODE ? g_h : g_att;
    float*       out = QKV_MODE ? g_qkv : outp;

    int n0 = blockIdx.x * 64;
    int m0 = blockIdx.y * 64;
    int b  = blockIdx.z;
    const float* ib = inp + (size_t)b * CH * NSP;

    __shared__ float Ws[64][20];   // [m][k], pad 20 keeps float4 STS aligned + conflict-free
    __shared__ float Hs[16][64];   // [k][n]

    int tx = threadIdx.x & 15, ty = threadIdx.x >> 4;
    int wm  = threadIdx.x & 63,  wk4 = (threadIdx.x >> 6) * 4;
    int hk  = threadIdx.x >> 4,  hn4 = (threadIdx.x & 15) * 4;

    float acc[4][4] = {};

    for (int k0 = 0; k0 < CH; k0 += 16) {
        *(float4*)&Ws[wm][wk4] =
            *(const float4*)(W + (size_t)(m0 + wm) * CH + k0 + wk4);
        *(float4*)&Hs[hk][hn4] =
            *(const float4*)(ib + (size_t)(k0 + hk) * NSP + n0 + hn4);
        __syncthreads();
        #pragma unroll
        for (int kk = 0; kk < 16; kk++) {
            float a[4], bb[4];
            #pragma unroll
            for (int r = 0; r < 4; r++) a[r]  = Ws[ty + 16 * r][kk];
            #pragma unroll
            for (int c = 0; c < 4; c++) bb[c] = Hs[kk][tx + 16 * c];
            #pragma unroll
            for (int r = 0; r < 4; r++)
                #pragma unroll
                for (int c = 0; c < 4; c++)
                    acc[r][c] += a[r] * bb[c];
        }
        __syncthreads();
    }

    #pragma unroll
    for (int r = 0; r < 4; r++) {
        int m = m0 + ty + 16 * r;
        float bv = bias[m];
        float* orow = out + ((size_t)b * MOUT + m) * NSP + n0;
        const float* rrow = QKV_MODE ? (const float*)0
                                     : (resid + ((size_t)b * MOUT + m) * NSP + n0);
        #pragma unroll
        for (int c = 0; c < 4; c++) {
            int n = tx + 16 * c;
            float v = acc[r][c] + bv;
            if (!QKV_MODE) v += rrow[n];
            orow[n] = v;
        }
    }
}

// ---------------------------------------------------------------------------
// Flash-style attention: one block per (b, head, query-tile-of-64).
// q,k,v stay in natural [d][n] layout (direct float4 smem copies, no transpose).
// Online softmax; m/l replicated across the 16 tx lanes via shfl.xor (<16 stays
// inside the ty half-warp).
// ---------------------------------------------------------------------------
__global__ void __launch_bounds__(256, 2)
attn_kernel() {
    int qt = blockIdx.x, hh = blockIdx.y, b = blockIdx.z;
    const float* qb = g_qkv + ((size_t)b * 3 * CH + hh * 3 * HD) * NSP;
    const float* kb = qb + (size_t)HD * NSP;
    const float* vb = qb + (size_t)2 * HD * NSP;

    extern __shared__ float sm[];
    float (*Qs)[64] = (float(*)[64])(sm);                       // [d][i]
    float (*Ks)[64] = (float(*)[64])(sm + 4096);                // [d][j]
    float (*Vs)[68] = (float(*)[68])(sm + 8192);                // [d][j] pad 68
    float (*Ps)[64] = (float(*)[64])(sm + 8192 + 64 * 68);      // [i][j]

    int tx = threadIdx.x & 15, ty = threadIdx.x >> 4;
    int n0 = qt * 64;

    // Load Q tile (direct copy, contiguous n)
    for (int idx = threadIdx.x; idx < 1024; idx += 256) {
        int dd = idx >> 4, i4 = (idx & 15) * 4;
        *(float4*)&Qs[dd][i4] = *(const float4*)(qb + (size_t)dd * NSP + n0 + i4);
    }

    float mi[4], li[4], acc[4][4];
    #pragma unroll
    for (int r = 0; r < 4; r++) {
        mi[r] = -INFINITY; li[r] = 0.f;
        #pragma unroll
        for (int c = 0; c < 4; c++) acc[r][c] = 0.f;
    }

    for (int t = 0; t < 16; t++) {
        int j0 = t * 64;
        for (int idx = threadIdx.x; idx < 1024; idx += 256) {
            int dd = idx >> 4, j4 = (idx & 15) * 4;
            *(float4*)&Ks[dd][j4] = *(const float4*)(kb + (size_t)dd * NSP + j0 + j4);
            *(float4*)&Vs[dd][j4] = *(const float4*)(vb + (size_t)dd * NSP + j0 + j4);
        }
        __syncthreads();

        // S = Q^T K (over d)
        float s[4][4] = {};
        #pragma unroll 8
        for (int dd = 0; dd < 64; dd++) {
            float a[4], bb[4];
            #pragma unroll
            for (int r = 0; r < 4; r++) a[r]  = Qs[dd][ty + 16 * r];
            #pragma unroll
            for (int c = 0; c < 4; c++) bb[c] = Ks[dd][tx + 16 * c];
            #pragma unroll
            for (int r = 0; r < 4; r++)
                #pragma unroll
                for (int c = 0; c < 4; c++)
                    s[r][c] += a[r] * bb[c];
        }

        // Online softmax per query row (rows owned by ty group, reduce over tx)
        #pragma unroll
        for (int r = 0; r < 4; r++) {
            float rm = -INFINITY;
            #pragma unroll
            for (int c = 0; c < 4; c++) {
                s[r][c] *= 0.125f;                 // d^-0.5
                rm = fmaxf(rm, s[r][c]);
            }
            #pragma unroll
            for (int o = 8; o > 0; o >>= 1)
                rm = fmaxf(rm, __shfl_xor_sync(0xffffffffu, rm, o));
            float mn = fmaxf(mi[r], rm);
            float al = __expf(mi[r] - mn);
            mi[r] = mn;
            float rsum = 0.f;
            #pragma unroll
            for (int c = 0; c < 4; c++) {
                float p = __expf(s[r][c] - mn);
                Ps[ty + 16 * r][tx + 16 * c] = p;
                rsum += p;
            }
            #pragma unroll
            for (int o = 8; o > 0; o >>= 1)
                rsum += __shfl_xor_sync(0xffffffffu, rsum, o);
            li[r] = li[r] * al + rsum;
            #pragma unroll
            for (int c = 0; c < 4; c++) acc[r][c] *= al;
        }
        __syncthreads();

        // O += P V^T : acc[r][c] over (query i = ty+16r, channel dc = tx+16c)
        #pragma unroll 4
        for (int j = 0; j < 64; j += 4) {
            float4 p4[4], v4[4];
            #pragma unroll
            for (int r = 0; r < 4; r++) p4[r] = *(float4*)&Ps[ty + 16 * r][j];
            #pragma unroll
            for (int c = 0; c < 4; c++) v4[c] = *(float4*)&Vs[tx + 16 * c][j];
            #pragma unroll
            for (int r = 0; r < 4; r++)
                #pragma unroll
                for (int c = 0; c < 4; c++)
                    acc[r][c] += p4[r].x * v4[c].x + p4[r].y * v4[c].y
                               + p4[r].z * v4[c].z + p4[r].w * v4[c].w;
        }
        __syncthreads();
    }

    // Normalize and stage through smem ([dc][i]) for coalesced store
    #pragma unroll
    for (int r = 0; r < 4; r++) {
        float inv = 1.f / li[r];
        #pragma unroll
        for (int c = 0; c < 4; c++)
            Ps[tx + 16 * c][ty + 16 * r] = acc[r][c] * inv;
    }
    __syncthreads();
    float* ob = g_att + ((size_t)b * CH + hh * HD) * NSP + n0;
    for (int idx = threadIdx.x; idx < 1024; idx += 256) {
        int dc = idx >> 4, i4 = (idx & 15) * 4;
        *(float4*)(ob + (size_t)dc * NSP + i4) = *(float4*)&Ps[dc][i4];
    }
}

// ---------------------------------------------------------------------------

static const int ATT_SMEM = (4096 + 4096 + 64 * 68 + 4096) * 4;   // 66560 B

extern "C" void kernel_launch(void* const* d_in, const int* in_sizes, int n_in,
                              void* d_out, int out_size) {
    const float* x      = (const float*)d_in[0];
    const float* gamma  = (const float*)d_in[1];
    const float* beta   = (const float*)d_in[2];
    const float* qkv_w  = (const float*)d_in[3];
    const float* qkv_b  = (const float*)d_in[4];
    const float* proj_w = (const float*)d_in[5];
    const float* proj_b = (const float*)d_in[6];
    float* out = (float*)d_out;

    cudaFuncSetAttribute(attn_kernel,
                         cudaFuncAttributeMaxDynamicSharedMemorySize, ATT_SMEM);

    gn_kernel<<<BATCH * NGRP, 256>>>(x, gamma, beta);
    gemm_kernel<768, true ><<<dim3(NSP / 64, 12, BATCH), 256>>>(qkv_w, qkv_b, 0, 0);
    attn_kernel<<<dim3(NSP / 64, NHEADS, BATCH), 256, ATT_SMEM>>>();
    gemm_kernel<256, false><<<dim3(NSP / 64, 4, BATCH), 256>>>(proj_w, proj_b, x, out);
}

// round 6
// speedup vs baseline: 1.5515x; 1.5515x over previous
#include <cuda_runtime.h>
#include <cuda_pipeline.h>
#include <mma.h>
#include <math.h>

using namespace nvcuda;

#define BATCH  16
#define CH     256
#define NSP    1024      // H*W
#define NHEADS 4
#define HD     64
#define NGRP   32
#define CPG    8

// Scratch (allocation-free: __device__ globals)
__device__ float g_h  [BATCH * CH * NSP];
__device__ float g_qkv[BATCH * 3 * CH * NSP];
__device__ float g_att[BATCH * CH * NSP];

// ---------------------------------------------------------------------------
// GroupNorm
// ---------------------------------------------------------------------------
__global__ void __launch_bounds__(256)
gn_kernel(const float* __restrict__ x,
          const float* __restrict__ gamma,
          const float* __restrict__ beta) {
    int b = blockIdx.x >> 5;
    int g = blockIdx.x & 31;
    const float4* xb = (const float4*)(x + ((size_t)b * CH + g * CPG) * NSP);
    float4*       hb = (float4*)(g_h + ((size_t)b * CH + g * CPG) * NSP);

    float s = 0.f, s2 = 0.f;
    for (int i = threadIdx.x; i < 2048; i += 256) {
        float4 v = xb[i];
        s  += v.x + v.y + v.z + v.w;
        s2 += v.x * v.x + v.y * v.y + v.z * v.z + v.w * v.w;
    }
    __shared__ float rs[256], rq[256];
    rs[threadIdx.x] = s; rq[threadIdx.x] = s2;
    __syncthreads();
    for (int o = 128; o > 0; o >>= 1) {
        if (threadIdx.x < o) {
            rs[threadIdx.x] += rs[threadIdx.x + o];
            rq[threadIdx.x] += rq[threadIdx.x + o];
        }
        __syncthreads();
    }
    __shared__ float mu_s, rstd_s;
    if (threadIdx.x == 0) {
        float mu  = rs[0] * (1.f / 8192.f);
        float var = rq[0] * (1.f / 8192.f) - mu * mu;
        mu_s = mu;
        rstd_s = rsqrtf(var + 1e-5f);
    }
    __syncthreads();
    float mu = mu_s, rstd = rstd_s;
    for (int i = threadIdx.x; i < 2048; i += 256) {
        int c = g * CPG + (i >> 8);
        float ga = gamma[c] * rstd;
        float be = beta[c] - mu * ga;
        float4 v = xb[i];
        v.x = v.x * ga + be; v.y = v.y * ga + be;
        v.z = v.z * ga + be; v.w = v.w * ga + be;
        hb[i] = v;
    }
}

// ---------------------------------------------------------------------------
// tf32 tensor-core channel GEMM: out[b,m,n] = sum_k W[m,k]*inp[b,k,n] (+bias,+resid)
// Block tile 64M x 128N, 8 warps (2x4), each 32x32 (2x2 wmma 16x16x8 frags).
// K chunks of 32, double-buffered via cp.async.
// ---------------------------------------------------------------------------
#define GM_LDW 36
#define GM_LDB 132
#define WS_SZ  (64 * GM_LDW)   // 2304
#define BS_SZ  (32 * GM_LDB)   // 4224
#define GM_SMEM_FLOATS (2 * WS_SZ + 2 * BS_SZ)   // 13056 floats -> 52224 B

template<int MOUT, bool QKV_MODE>
__global__ void __launch_bounds__(256)
gemm_tc(const float* __restrict__ W, const float* __restrict__ bias,
        const float* __restrict__ resid, float* __restrict__ outp) {
    extern __shared__ float sm[];
    float* Wbuf = sm;
    float* Bbuf = sm + 2 * WS_SZ;

    const float* inp = QKV_MODE ? g_h : g_att;
    float*       out = QKV_MODE ? g_qkv : outp;

    int n0 = blockIdx.x * 128;
    int m0 = blockIdx.y * 64;
    int b  = blockIdx.z;
    const float* ib = inp + (size_t)b * CH * NSP;

    int warp = threadIdx.x >> 5;
    int wm = (warp & 1) * 32;
    int wn = (warp >> 1) * 32;

    wmma::fragment<wmma::accumulator, 16, 16, 8, float> cf[2][2];
    #pragma unroll
    for (int r = 0; r < 2; r++)
        #pragma unroll
        for (int c = 0; c < 2; c++) wmma::fill_fragment(cf[r][c], 0.f);

    auto issue = [&](int ch) {
        float* ws = Wbuf + (ch & 1) * WS_SZ;
        float* bs = Bbuf + (ch & 1) * BS_SZ;
        int k0 = ch * 32;
        #pragma unroll
        for (int idx = threadIdx.x; idx < 512; idx += 256) {
            int row = idx >> 3, k4 = (idx & 7) * 4;
            __pipeline_memcpy_async(ws + row * GM_LDW + k4,
                W + (size_t)(m0 + row) * CH + k0 + k4, 16);
        }
        #pragma unroll
        for (int idx = threadIdx.x; idx < 1024; idx += 256) {
            int row = idx >> 5, n4 = (idx & 31) * 4;
            __pipeline_memcpy_async(bs + row * GM_LDB + n4,
                ib + (size_t)(k0 + row) * NSP + n0 + n4, 16);
        }
        __pipeline_commit();
    };

    issue(0);
    for (int ch = 0; ch < 8; ch++) {
        float* ws = Wbuf + (ch & 1) * WS_SZ;
        float* bs = Bbuf + (ch & 1) * BS_SZ;
        __pipeline_wait_prior(0);
        __syncthreads();
        if (ch < 7) issue(ch + 1);
        #pragma unroll
        for (int kk = 0; kk < 32; kk += 8) {
            wmma::fragment<wmma::matrix_a, 16, 16, 8, wmma::precision::tf32, wmma::row_major> af[2];
            wmma::fragment<wmma::matrix_b, 16, 16, 8, wmma::precision::tf32, wmma::row_major> bf[2];
            #pragma unroll
            for (int r = 0; r < 2; r++) {
                wmma::load_matrix_sync(af[r], ws + (wm + 16 * r) * GM_LDW + kk, GM_LDW);
                #pragma unroll
                for (int i = 0; i < af[r].num_elements; i++)
                    af[r].x[i] = wmma::__float_to_tf32(af[r].x[i]);
            }
            #pragma unroll
            for (int c = 0; c < 2; c++) {
                wmma::load_matrix_sync(bf[c], bs + kk * GM_LDB + wn + 16 * c, GM_LDB);
                #pragma unroll
                for (int i = 0; i < bf[c].num_elements; i++)
                    bf[c].x[i] = wmma::__float_to_tf32(bf[c].x[i]);
            }
            #pragma unroll
            for (int r = 0; r < 2; r++)
                #pragma unroll
                for (int c = 0; c < 2; c++)
                    wmma::mma_sync(cf[r][c], af[r], bf[c], cf[r][c]);
        }
        __syncthreads();
    }

    // Epilogue: stage into smem (reuse buffers), add bias/resid, coalesced store
    float* Ss = sm;   // 64 x GM_LDB
    #pragma unroll
    for (int r = 0; r < 2; r++)
        #pragma unroll
        for (int c = 0; c < 2; c++)
            wmma::store_matrix_sync(Ss + (wm + 16 * r) * GM_LDB + wn + 16 * c,
                                    cf[r][c], GM_LDB, wmma::mem_row_major);
    __syncthreads();
    for (int idx = threadIdx.x; idx < 2048; idx += 256) {
        int row = idx >> 5, n4 = (idx & 31) * 4;
        int m = m0 + row;
        float4 v = *(float4*)(Ss + row * GM_LDB + n4);
        float bv = bias[m];
        v.x += bv; v.y += bv; v.z += bv; v.w += bv;
        if (!QKV_MODE) {
            float4 rr = *(const float4*)(resid + ((size_t)b * MOUT + m) * NSP + n0 + n4);
            v.x += rr.x; v.y += rr.y; v.z += rr.z; v.w += rr.w;
        }
        *(float4*)(out + ((size_t)b * MOUT + m) * NSP + n0 + n4) = v;
    }
}

// ---------------------------------------------------------------------------
// tf32 tensor-core flash attention: block = (b, head, 64-query tile).
// S = Q^T K and O += P V^T via wmma straight out of the [d][n]-layout tiles.
// Online softmax scalar in smem (4 threads per query row).
// ---------------------------------------------------------------------------
#define AT_LD 72
#define Q_OFF 0
#define K_OFF (64 * AT_LD)
#define V_OFF (2 * 64 * AT_LD)
#define P_OFF (3 * 64 * AT_LD)
#define O_OFF (4 * 64 * AT_LD)
#define M_OFF (5 * 64 * AT_LD)
#define L_OFF (M_OFF + 64)
#define ATT_FLOATS (L_OFF + 64)     // 23168 floats -> 92672 B

__global__ void __launch_bounds__(256)
attn_tc() {
    extern __shared__ float sm[];
    int qt = blockIdx.x, hh = blockIdx.y, b = blockIdx.z;
    const float* qb = g_qkv + ((size_t)b * 3 * CH + hh * 3 * HD) * NSP;
    const float* kb = qb + (size_t)HD * NSP;
    const float* vb = qb + (size_t)2 * HD * NSP;
    int n0 = qt * 64;
    int warp = threadIdx.x >> 5;

    // Load Q tile [d][i]; zero O; init m/l
    for (int idx = threadIdx.x; idx < 1024; idx += 256) {
        int dd = idx >> 4, i4 = (idx & 15) * 4;
        *(float4*)(sm + Q_OFF + dd * AT_LD + i4) =
            *(const float4*)(qb + (size_t)dd * NSP + n0 + i4);
    }
    for (int idx = threadIdx.x; idx < 64 * AT_LD / 4; idx += 256)
        *(float4*)(sm + O_OFF + idx * 4) = make_float4(0.f, 0.f, 0.f, 0.f);
    if (threadIdx.x < 64) { sm[M_OFF + threadIdx.x] = -INFINITY; sm[L_OFF + threadIdx.x] = 0.f; }

    int fi = (warp >> 2) * 16;   // warp's i-frag offsets: fi and fi+32
    int fj = (warp & 3) * 16;    // warp's j / dc frag offset

    for (int t = 0; t < 16; t++) {
        int j0 = t * 64;
        for (int idx = threadIdx.x; idx < 1024; idx += 256) {
            int dd = idx >> 4, j4 = (idx & 15) * 4;
            *(float4*)(sm + K_OFF + dd * AT_LD + j4) =
                *(const float4*)(kb + (size_t)dd * NSP + j0 + j4);
            *(float4*)(sm + V_OFF + dd * AT_LD + j4) =
                *(const float4*)(vb + (size_t)dd * NSP + j0 + j4);
        }
        __syncthreads();

        // S = Q^T K : A = Q (col_major view of [d][i]), B = K (row_major [d][j])
        {
            wmma::fragment<wmma::accumulator, 16, 16, 8, float> s0, s1;
            wmma::fill_fragment(s0, 0.f); wmma::fill_fragment(s1, 0.f);
            #pragma unroll
            for (int kk = 0; kk < 64; kk += 8) {
                wmma::fragment<wmma::matrix_a, 16, 16, 8, wmma::precision::tf32, wmma::col_major> a0, a1;
                wmma::fragment<wmma::matrix_b, 16, 16, 8, wmma::precision::tf32, wmma::row_major> bf;
                wmma::load_matrix_sync(a0, sm + Q_OFF + kk * AT_LD + fi, AT_LD);
                wmma::load_matrix_sync(a1, sm + Q_OFF + kk * AT_LD + fi + 32, AT_LD);
                wmma::load_matrix_sync(bf, sm + K_OFF + kk * AT_LD + fj, AT_LD);
                #pragma unroll
                for (int i = 0; i < a0.num_elements; i++) {
                    a0.x[i] = wmma::__float_to_tf32(a0.x[i]);
                    a1.x[i] = wmma::__float_to_tf32(a1.x[i]);
                }
                #pragma unroll
                for (int i = 0; i < bf.num_elements; i++)
                    bf.x[i] = wmma::__float_to_tf32(bf.x[i]);
                wmma::mma_sync(s0, a0, bf, s0);
                wmma::mma_sync(s1, a1, bf, s1);
            }
            wmma::store_matrix_sync(sm + P_OFF + fi * AT_LD + fj, s0, AT_LD, wmma::mem_row_major);
            wmma::store_matrix_sync(sm + P_OFF + (fi + 32) * AT_LD + fj, s1, AT_LD, wmma::mem_row_major);
        }
        __syncthreads();

        // Online softmax: 4 threads per query row
        {
            int row = threadIdx.x >> 2, sub = threadIdx.x & 3;
            float* prow = sm + P_OFF + row * AT_LD;
            float v[16];
            float mx = -INFINITY;
            #pragma unroll
            for (int j = 0; j < 16; j++) {
                v[j] = prow[sub + 4 * j] * 0.125f;     // d^-0.5
                mx = fmaxf(mx, v[j]);
            }
            mx = fmaxf(mx, __shfl_xor_sync(0xffffffffu, mx, 1));
            mx = fmaxf(mx, __shfl_xor_sync(0xffffffffu, mx, 2));
            float mold = sm[M_OFF + row];
            float mnew = fmaxf(mold, mx);
            float alpha = __expf(mold - mnew);
            float ssum = 0.f;
            #pragma unroll
            for (int j = 0; j < 16; j++) {
                float p = __expf(v[j] - mnew);
                prow[sub + 4 * j] = p;
                ssum += p;
            }
            ssum += __shfl_xor_sync(0xffffffffu, ssum, 1);
            ssum += __shfl_xor_sync(0xffffffffu, ssum, 2);
            float* orow = sm + O_OFF + row * AT_LD;
            #pragma unroll
            for (int j = 0; j < 16; j++) orow[sub + 4 * j] *= alpha;
            if (sub == 0) {
                sm[M_OFF + row] = mnew;
                sm[L_OFF + row] = sm[L_OFF + row] * alpha + ssum;
            }
        }
        __syncthreads();

        // O += P V^T : A = P (row_major [i][j]), B = V (col_major view of [dc][j])
        {
            wmma::fragment<wmma::accumulator, 16, 16, 8, float> o0, o1;
            wmma::load_matrix_sync(o0, sm + O_OFF + fi * AT_LD + fj, AT_LD, wmma::mem_row_major);
            wmma::load_matrix_sync(o1, sm + O_OFF + (fi + 32) * AT_LD + fj, AT_LD, wmma::mem_row_major);
            #pragma unroll
            for (int jk = 0; jk < 64; jk += 8) {
                wmma::fragment<wmma::matrix_a, 16, 16, 8, wmma::precision::tf32, wmma::row_major> a0, a1;
                wmma::fragment<wmma::matrix_b, 16, 16, 8, wmma::precision::tf32, wmma::col_major> bf;
                wmma::load_matrix_sync(a0, sm + P_OFF + fi * AT_LD + jk, AT_LD);
                wmma::load_matrix_sync(a1, sm + P_OFF + (fi + 32) * AT_LD + jk, AT_LD);
                wmma::load_matrix_sync(bf, sm + V_OFF + fj * AT_LD + jk, AT_LD);
                #pragma unroll
                for (int i = 0; i < a0.num_elements; i++) {
                    a0.x[i] = wmma::__float_to_tf32(a0.x[i]);
                    a1.x[i] = wmma::__float_to_tf32(a1.x[i]);
                }
                #pragma unroll
                for (int i = 0; i < bf.num_elements; i++)
                    bf.x[i] = wmma::__float_to_tf32(bf.x[i]);
                wmma::mma_sync(o0, a0, bf, o0);
                wmma::mma_sync(o1, a1, bf, o1);
            }
            wmma::store_matrix_sync(sm + O_OFF + fi * AT_LD + fj, o0, AT_LD, wmma::mem_row_major);
            wmma::store_matrix_sync(sm + O_OFF + (fi + 32) * AT_LD + fj, o1, AT_LD, wmma::mem_row_major);
        }
        __syncthreads();
    }

    // Normalize and store transposed ([i][dc] smem -> [dc][i] gmem)
    if (threadIdx.x < 64) sm[M_OFF + threadIdx.x] = 1.f / sm[L_OFF + threadIdx.x];
    __syncthreads();
    float* ob = g_att + ((size_t)b * CH + hh * HD) * NSP + n0;
    for (int idx = threadIdx.x; idx < 4096; idx += 256) {
        int dc = idx >> 6, i = idx & 63;
        ob[(size_t)dc * NSP + i] = sm[O_OFF + i * AT_LD + dc] * sm[M_OFF + i];
    }
}

// ---------------------------------------------------------------------------

extern "C" void kernel_launch(void* const* d_in, const int* in_sizes, int n_in,
                              void* d_out, int out_size) {
    const float* x      = (const float*)d_in[0];
    const float* gamma  = (const float*)d_in[1];
    const float* beta   = (const float*)d_in[2];
    const float* qkv_w  = (const float*)d_in[3];
    const float* qkv_b  = (const float*)d_in[4];
    const float* proj_w = (const float*)d_in[5];
    const float* proj_b = (const float*)d_in[6];
    float* out = (float*)d_out;

    const int gm_smem  = GM_SMEM_FLOATS * 4;
    const int att_smem = ATT_FLOATS * 4;

    cudaFuncSetAttribute(gemm_tc<768, true>,
                         cudaFuncAttributeMaxDynamicSharedMemorySize, gm_smem);
    cudaFuncSetAttribute(gemm_tc<256, false>,
                         cudaFuncAttributeMaxDynamicSharedMemorySize, gm_smem);
    cudaFuncSetAttribute(attn_tc,
                         cudaFuncAttributeMaxDynamicSharedMemorySize, att_smem);

    gn_kernel<<<BATCH * NGRP, 256>>>(x, gamma, beta);
    gemm_tc<768, true ><<<dim3(NSP / 128, 12, BATCH), 256, gm_smem>>>(qkv_w, qkv_b, 0, 0);
    attn_tc<<<dim3(NSP / 64, NHEADS, BATCH), 256, att_smem>>>();
    gemm_tc<256, false><<<dim3(NSP / 128, 4, BATCH), 256, gm_smem>>>(proj_w, proj_b, x, out);
}

// round 7
// speedup vs baseline: 2.6172x; 1.6869x over previous
#include <cuda_runtime.h>
#include <cuda_pipeline.h>
#include <mma.h>
#include <math.h>
#include <stdint.h>

using namespace nvcuda;

#define BATCH  16
#define CH     256
#define NSP    1024      // H*W
#define NHEADS 4
#define HD     64
#define NGRP   32
#define CPG    8

// Scratch (allocation-free: __device__ globals)
__device__ float g_h  [BATCH * CH * NSP];
__device__ float g_qkv[BATCH * 3 * CH * NSP];
__device__ float g_att[BATCH * CH * NSP];

// ---------------------------------------------------------------------------
// GroupNorm
// ---------------------------------------------------------------------------
__global__ void __launch_bounds__(256)
gn_kernel(const float* __restrict__ x,
          const float* __restrict__ gamma,
          const float* __restrict__ beta) {
    int b = blockIdx.x >> 5;
    int g = blockIdx.x & 31;
    const float4* xb = (const float4*)(x + ((size_t)b * CH + g * CPG) * NSP);
    float4*       hb = (float4*)(g_h + ((size_t)b * CH + g * CPG) * NSP);

    float s = 0.f, s2 = 0.f;
    for (int i = threadIdx.x; i < 2048; i += 256) {
        float4 v = xb[i];
        s  += v.x + v.y + v.z + v.w;
        s2 += v.x * v.x + v.y * v.y + v.z * v.z + v.w * v.w;
    }
    __shared__ float rs[256], rq[256];
    rs[threadIdx.x] = s; rq[threadIdx.x] = s2;
    __syncthreads();
    for (int o = 128; o > 0; o >>= 1) {
        if (threadIdx.x < o) {
            rs[threadIdx.x] += rs[threadIdx.x + o];
            rq[threadIdx.x] += rq[threadIdx.x + o];
        }
        __syncthreads();
    }
    __shared__ float mu_s, rstd_s;
    if (threadIdx.x == 0) {
        float mu  = rs[0] * (1.f / 8192.f);
        float var = rq[0] * (1.f / 8192.f) - mu * mu;
        mu_s = mu;
        rstd_s = rsqrtf(var + 1e-5f);
    }
    __syncthreads();
    float mu = mu_s, rstd = rstd_s;
    for (int i = threadIdx.x; i < 2048; i += 256) {
        int c = g * CPG + (i >> 8);
        float ga = gamma[c] * rstd;
        float be = beta[c] - mu * ga;
        float4 v = xb[i];
        v.x = v.x * ga + be; v.y = v.y * ga + be;
        v.z = v.z * ga + be; v.w = v.w * ga + be;
        hb[i] = v;
    }
}

// ---------------------------------------------------------------------------
// tf32 tensor-core channel GEMM (unchanged from passing R6 kernel)
// ---------------------------------------------------------------------------
#define GM_LDW 36
#define GM_LDB 132
#define WS_SZ  (64 * GM_LDW)
#define BS_SZ  (32 * GM_LDB)
#define GM_SMEM_FLOATS (2 * WS_SZ + 2 * BS_SZ)

template<int MOUT, bool QKV_MODE>
__global__ void __launch_bounds__(256)
gemm_tc(const float* __restrict__ W, const float* __restrict__ bias,
        const float* __restrict__ resid, float* __restrict__ outp) {
    extern __shared__ float sm[];
    float* Wbuf = sm;
    float* Bbuf = sm + 2 * WS_SZ;

    const float* inp = QKV_MODE ? g_h : g_att;
    float*       out = QKV_MODE ? g_qkv : outp;

    int n0 = blockIdx.x * 128;
    int m0 = blockIdx.y * 64;
    int b  = blockIdx.z;
    const float* ib = inp + (size_t)b * CH * NSP;

    int warp = threadIdx.x >> 5;
    int wm = (warp & 1) * 32;
    int wn = (warp >> 1) * 32;

    wmma::fragment<wmma::accumulator, 16, 16, 8, float> cf[2][2];
    #pragma unroll
    for (int r = 0; r < 2; r++)
        #pragma unroll
        for (int c = 0; c < 2; c++) wmma::fill_fragment(cf[r][c], 0.f);

    auto issue = [&](int ch) {
        float* ws = Wbuf + (ch & 1) * WS_SZ;
        float* bs = Bbuf + (ch & 1) * BS_SZ;
        int k0 = ch * 32;
        #pragma unroll
        for (int idx = threadIdx.x; idx < 512; idx += 256) {
            int row = idx >> 3, k4 = (idx & 7) * 4;
            __pipeline_memcpy_async(ws + row * GM_LDW + k4,
                W + (size_t)(m0 + row) * CH + k0 + k4, 16);
        }
        #pragma unroll
        for (int idx = threadIdx.x; idx < 1024; idx += 256) {
            int row = idx >> 5, n4 = (idx & 31) * 4;
            __pipeline_memcpy_async(bs + row * GM_LDB + n4,
                ib + (size_t)(k0 + row) * NSP + n0 + n4, 16);
        }
        __pipeline_commit();
    };

    issue(0);
    for (int ch = 0; ch < 8; ch++) {
        float* ws = Wbuf + (ch & 1) * WS_SZ;
        float* bs = Bbuf + (ch & 1) * BS_SZ;
        __pipeline_wait_prior(0);
        __syncthreads();
        if (ch < 7) issue(ch + 1);
        #pragma unroll
        for (int kk = 0; kk < 32; kk += 8) {
            wmma::fragment<wmma::matrix_a, 16, 16, 8, wmma::precision::tf32, wmma::row_major> af[2];
            wmma::fragment<wmma::matrix_b, 16, 16, 8, wmma::precision::tf32, wmma::row_major> bf[2];
            #pragma unroll
            for (int r = 0; r < 2; r++) {
                wmma::load_matrix_sync(af[r], ws + (wm + 16 * r) * GM_LDW + kk, GM_LDW);
                #pragma unroll
                for (int i = 0; i < af[r].num_elements; i++)
                    af[r].x[i] = wmma::__float_to_tf32(af[r].x[i]);
            }
            #pragma unroll
            for (int c = 0; c < 2; c++) {
                wmma::load_matrix_sync(bf[c], bs + kk * GM_LDB + wn + 16 * c, GM_LDB);
                #pragma unroll
                for (int i = 0; i < bf[c].num_elements; i++)
                    bf[c].x[i] = wmma::__float_to_tf32(bf[c].x[i]);
            }
            #pragma unroll
            for (int r = 0; r < 2; r++)
                #pragma unroll
                for (int c = 0; c < 2; c++)
                    wmma::mma_sync(cf[r][c], af[r], bf[c], cf[r][c]);
        }
        __syncthreads();
    }

    float* Ss = sm;
    #pragma unroll
    for (int r = 0; r < 2; r++)
        #pragma unroll
        for (int c = 0; c < 2; c++)
            wmma::store_matrix_sync(Ss + (wm + 16 * r) * GM_LDB + wn + 16 * c,
                                    cf[r][c], GM_LDB, wmma::mem_row_major);
    __syncthreads();
    for (int idx = threadIdx.x; idx < 2048; idx += 256) {
        int row = idx >> 5, n4 = (idx & 31) * 4;
        int m = m0 + row;
        float4 v = *(float4*)(Ss + row * GM_LDB + n4);
        float bv = bias[m];
        v.x += bv; v.y += bv; v.z += bv; v.w += bv;
        if (!QKV_MODE) {
            float4 rr = *(const float4*)(resid + ((size_t)b * MOUT + m) * NSP + n0 + n4);
            v.x += rr.x; v.y += rr.y; v.z += rr.z; v.w += rr.w;
        }
        *(float4*)(out + ((size_t)b * MOUT + m) * NSP + n0 + n4) = v;
    }
}

// ---------------------------------------------------------------------------
// Register-resident flash attention, raw PTX mma.m16n8k8 tf32.
// Block = (b, head, 128-query tile), 8 warps; warp owns 16 q-rows.
// O accumulators + m/l in registers; only P transits smem (aliases K tile).
// ---------------------------------------------------------------------------
#define LDQ 136
#define LDP 72
#define LDV 68
#define QS_OFF 0
#define PS_OFF (64 * LDQ)                 // 8704 ; [128][72] (K tile aliased)
#define VS_OFF (PS_OFF + 128 * LDP)       // 17920; [64][68]
#define AT2_FLOATS (VS_OFF + 64 * LDV)    // 22272 floats -> 89088 B

__device__ __forceinline__ void mma8(float d[4],
    uint32_t a0, uint32_t a1, uint32_t a2, uint32_t a3,
    uint32_t b0, uint32_t b1) {
    asm volatile(
        "mma.sync.aligned.m16n8k8.row.col.f32.tf32.tf32.f32 "
        "{%0,%1,%2,%3}, {%4,%5,%6,%7}, {%8,%9}, {%0,%1,%2,%3};\n"
        : "+f"(d[0]), "+f"(d[1]), "+f"(d[2]), "+f"(d[3])
        : "r"(a0), "r"(a1), "r"(a2), "r"(a3), "r"(b0), "r"(b1));
}

__global__ void __launch_bounds__(256)
attn_reg() {
    extern __shared__ float sm[];
    float* Qs = sm + QS_OFF;
    float* Ps = sm + PS_OFF;   // K tile lives here too (first 64 rows)
    float* Vs = sm + VS_OFF;

    int qt = blockIdx.x, hh = blockIdx.y, b = blockIdx.z;
    const float* qb = g_qkv + ((size_t)b * 3 * CH + hh * 3 * HD) * NSP;
    const float* kb = qb + (size_t)HD * NSP;
    const float* vb = qb + (size_t)2 * HD * NSP;
    int n0 = qt * 128;

    int lane = threadIdx.x & 31, warp = threadIdx.x >> 5;
    int g = lane >> 2, t = lane & 3;
    int iw = warp * 16;              // warp's query-row base

    // Q tile [64 d][128 i], scale 1/sqrt(d)=0.125 folded in
    for (int idx = threadIdx.x; idx < 2048; idx += 256) {
        int dd = idx >> 5, i4 = (idx & 31) * 4;
        float4 v = *(const float4*)(qb + (size_t)dd * NSP + n0 + i4);
        v.x *= 0.125f; v.y *= 0.125f; v.z *= 0.125f; v.w *= 0.125f;
        *(float4*)(Qs + dd * LDQ + i4) = v;
    }

    float o[8][4];
    #pragma unroll
    for (int n = 0; n < 8; n++)
        #pragma unroll
        for (int c = 0; c < 4; c++) o[n][c] = 0.f;
    float m0 = -INFINITY, m1 = -INFINITY, l0 = 0.f, l1 = 0.f;

    for (int tile = 0; tile < 16; tile++) {
        int j0 = tile * 64;
        // K into Ps region [64][LDP], V into Vs [64][LDV]
        for (int idx = threadIdx.x; idx < 1024; idx += 256) {
            int dd = idx >> 4, j4 = (idx & 15) * 4;
            *(float4*)(Ps + dd * LDP + j4) = *(const float4*)(kb + (size_t)dd * NSP + j0 + j4);
            *(float4*)(Vs + dd * LDV + j4) = *(const float4*)(vb + (size_t)dd * NSP + j0 + j4);
        }
        __syncthreads();

        // S = (Q*scale)^T K   : A(i,k)=Q[d0+k][iw+i], B(k,n)=K[d0+k][n8+n]
        float s[8][4];
        #pragma unroll
        for (int n = 0; n < 8; n++)
            #pragma unroll
            for (int c = 0; c < 4; c++) s[n][c] = 0.f;
        #pragma unroll
        for (int k = 0; k < 8; k++) {
            int d0 = k * 8;
            uint32_t a0 = __float_as_uint(Qs[(d0 + t)     * LDQ + iw + g]);
            uint32_t a1 = __float_as_uint(Qs[(d0 + t)     * LDQ + iw + g + 8]);
            uint32_t a2 = __float_as_uint(Qs[(d0 + t + 4) * LDQ + iw + g]);
            uint32_t a3 = __float_as_uint(Qs[(d0 + t + 4) * LDQ + iw + g + 8]);
            #pragma unroll
            for (int n = 0; n < 8; n++) {
                uint32_t b0 = __float_as_uint(Ps[(d0 + t)     * LDP + n * 8 + g]);
                uint32_t b1 = __float_as_uint(Ps[(d0 + t + 4) * LDP + n * 8 + g]);
                mma8(s[n], a0, a1, a2, a3, b0, b1);
            }
        }

        // In-register online softmax. Rows: iw+g (c0,c1), iw+g+8 (c2,c3);
        // row spread over the 4 lanes of this group -> shfl_xor 1,2.
        float mx0 = -INFINITY, mx1 = -INFINITY;
        #pragma unroll
        for (int n = 0; n < 8; n++) {
            mx0 = fmaxf(mx0, fmaxf(s[n][0], s[n][1]));
            mx1 = fmaxf(mx1, fmaxf(s[n][2], s[n][3]));
        }
        mx0 = fmaxf(mx0, __shfl_xor_sync(0xffffffffu, mx0, 1));
        mx0 = fmaxf(mx0, __shfl_xor_sync(0xffffffffu, mx0, 2));
        mx1 = fmaxf(mx1, __shfl_xor_sync(0xffffffffu, mx1, 1));
        mx1 = fmaxf(mx1, __shfl_xor_sync(0xffffffffu, mx1, 2));
        float mn0 = fmaxf(m0, mx0), mn1 = fmaxf(m1, mx1);
        float al0 = __expf(m0 - mn0), al1 = __expf(m1 - mn1);
        m0 = mn0; m1 = mn1;
        float r0 = 0.f, r1 = 0.f;
        #pragma unroll
        for (int n = 0; n < 8; n++) {
            s[n][0] = __expf(s[n][0] - mn0);
            s[n][1] = __expf(s[n][1] - mn0);
            s[n][2] = __expf(s[n][2] - mn1);
            s[n][3] = __expf(s[n][3] - mn1);
            r0 += s[n][0] + s[n][1];
            r1 += s[n][2] + s[n][3];
        }
        r0 += __shfl_xor_sync(0xffffffffu, r0, 1);
        r0 += __shfl_xor_sync(0xffffffffu, r0, 2);
        r1 += __shfl_xor_sync(0xffffffffu, r1, 1);
        r1 += __shfl_xor_sync(0xffffffffu, r1, 2);
        l0 = l0 * al0 + r0;
        l1 = l1 * al1 + r1;
        #pragma unroll
        for (int n = 0; n < 8; n++) {
            o[n][0] *= al0; o[n][1] *= al0;
            o[n][2] *= al1; o[n][3] *= al1;
        }
        __syncthreads();   // all warps finished reading K -> reuse region for P

        // Store P [128 i][64 j]: C frag cols are 2t,2t+1 -> float2 stores
        #pragma unroll
        for (int n = 0; n < 8; n++) {
            *(float2*)(Ps + (iw + g)     * LDP + n * 8 + 2 * t) = make_float2(s[n][0], s[n][1]);
            *(float2*)(Ps + (iw + g + 8) * LDP + n * 8 + 2 * t) = make_float2(s[n][2], s[n][3]);
        }
        __syncthreads();

        // O += P V^T : A(i,j)=P[iw+i][jj+j], B(j,dc)=V[n8+dc][jj+j]
        #pragma unroll
        for (int j = 0; j < 8; j++) {
            int jj = j * 8;
            uint32_t a0 = __float_as_uint(Ps[(iw + g)     * LDP + jj + t]);
            uint32_t a1 = __float_as_uint(Ps[(iw + g + 8) * LDP + jj + t]);
            uint32_t a2 = __float_as_uint(Ps[(iw + g)     * LDP + jj + t + 4]);
            uint32_t a3 = __float_as_uint(Ps[(iw + g + 8) * LDP + jj + t + 4]);
            #pragma unroll
            for (int n = 0; n < 8; n++) {
                uint32_t b0 = __float_as_uint(Vs[(n * 8 + g) * LDV + jj + t]);
                uint32_t b1 = __float_as_uint(Vs[(n * 8 + g) * LDV + jj + t + 4]);
                mma8(o[n], a0, a1, a2, a3, b0, b1);
            }
        }
        __syncthreads();   // done with Ps/Vs before next tile's load
    }

    // Normalize in registers, stage transposed [dc][i] in smem, store coalesced
    float inv0 = 1.f / l0, inv1 = 1.f / l1;
    #pragma unroll
    for (int n = 0; n < 8; n++) {
        o[n][0] *= inv0; o[n][1] *= inv0;
        o[n][2] *= inv1; o[n][3] *= inv1;
    }
    float* Os = Ps;        // [64 dc][132] (8448 floats <= 9216 region)
    #pragma unroll
    for (int n = 0; n < 8; n++) {
        int dc = n * 8 + 2 * t;
        Os[dc * 132 + iw + g]           = o[n][0];
        Os[(dc + 1) * 132 + iw + g]     = o[n][1];
        Os[dc * 132 + iw + g + 8]       = o[n][2];
        Os[(dc + 1) * 132 + iw + g + 8] = o[n][3];
    }
    __syncthreads();
    float* ob = g_att + ((size_t)b * CH + hh * HD) * NSP + n0;
    for (int idx = threadIdx.x; idx < 2048; idx += 256) {
        int dc = idx >> 5, i4 = (idx & 31) * 4;
        *(float4*)(ob + (size_t)dc * NSP + i4) = *(float4*)(Os + dc * 132 + i4);
    }
}

// ---------------------------------------------------------------------------

extern "C" void kernel_launch(void* const* d_in, const int* in_sizes, int n_in,
                              void* d_out, int out_size) {
    const float* x      = (const float*)d_in[0];
    const float* gamma  = (const float*)d_in[1];
    const float* beta   = (const float*)d_in[2];
    const float* qkv_w  = (const float*)d_in[3];
    const float* qkv_b  = (const float*)d_in[4];
    const float* proj_w = (const float*)d_in[5];
    const float* proj_b = (const float*)d_in[6];
    float* out = (float*)d_out;

    const int gm_smem  = GM_SMEM_FLOATS * 4;
    const int att_smem = AT2_FLOATS * 4;

    cudaFuncSetAttribute(gemm_tc<768, true>,
                         cudaFuncAttributeMaxDynamicSharedMemorySize, gm_smem);
    cudaFuncSetAttribute(gemm_tc<256, false>,
                         cudaFuncAttributeMaxDynamicSharedMemorySize, gm_smem);
    cudaFuncSetAttribute(attn_reg,
                         cudaFuncAttributeMaxDynamicSharedMemorySize, att_smem);

    gn_kernel<<<BATCH * NGRP, 256>>>(x, gamma, beta);
    gemm_tc<768, true ><<<dim3(NSP / 128, 12, BATCH), 256, gm_smem>>>(qkv_w, qkv_b, 0, 0);
    attn_reg<<<dim3(NSP / 128, NHEADS, BATCH), 256, att_smem>>>();
    gemm_tc<256, false><<<dim3(NSP / 128, 4, BATCH), 256, gm_smem>>>(proj_w, proj_b, x, out);
}

// round 8
// speedup vs baseline: 3.3330x; 1.2735x over previous
#include <cuda_runtime.h>
#include <cuda_pipeline.h>
#include <math.h>
#include <stdint.h>

#define BATCH  16
#define CH     256
#define NSP    1024      // H*W
#define NHEADS 4
#define HD     64
#define NGRP   32
#define CPG    8

// Scratch (allocation-free: __device__ globals)
__device__ float g_h  [BATCH * CH * NSP];
__device__ float g_qkv[BATCH * 3 * CH * NSP];
__device__ float g_att[BATCH * CH * NSP];

// ---------------------------------------------------------------------------
// m16n8k8 tf32 mma (raw fp32 bits in, fp32 accum)
// ---------------------------------------------------------------------------
__device__ __forceinline__ void mma8(float d[4],
    uint32_t a0, uint32_t a1, uint32_t a2, uint32_t a3,
    uint32_t b0, uint32_t b1) {
    asm volatile(
        "mma.sync.aligned.m16n8k8.row.col.f32.tf32.tf32.f32 "
        "{%0,%1,%2,%3}, {%4,%5,%6,%7}, {%8,%9}, {%0,%1,%2,%3};\n"
        : "+f"(d[0]), "+f"(d[1]), "+f"(d[2]), "+f"(d[3])
        : "r"(a0), "r"(a1), "r"(a2), "r"(a3), "r"(b0), "r"(b1));
}

// ---------------------------------------------------------------------------
// GroupNorm
// ---------------------------------------------------------------------------
__global__ void __launch_bounds__(256)
gn_kernel(const float* __restrict__ x,
          const float* __restrict__ gamma,
          const float* __restrict__ beta) {
    int b = blockIdx.x >> 5;
    int g = blockIdx.x & 31;
    const float4* xb = (const float4*)(x + ((size_t)b * CH + g * CPG) * NSP);
    float4*       hb = (float4*)(g_h + ((size_t)b * CH + g * CPG) * NSP);

    float s = 0.f, s2 = 0.f;
    for (int i = threadIdx.x; i < 2048; i += 256) {
        float4 v = xb[i];
        s  += v.x + v.y + v.z + v.w;
        s2 += v.x * v.x + v.y * v.y + v.z * v.z + v.w * v.w;
    }
    __shared__ float rs[256], rq[256];
    rs[threadIdx.x] = s; rq[threadIdx.x] = s2;
    __syncthreads();
    for (int o = 128; o > 0; o >>= 1) {
        if (threadIdx.x < o) {
            rs[threadIdx.x] += rs[threadIdx.x + o];
            rq[threadIdx.x] += rq[threadIdx.x + o];
        }
        __syncthreads();
    }
    __shared__ float mu_s, rstd_s;
    if (threadIdx.x == 0) {
        float mu  = rs[0] * (1.f / 8192.f);
        float var = rq[0] * (1.f / 8192.f) - mu * mu;
        mu_s = mu;
        rstd_s = rsqrtf(var + 1e-5f);
    }
    __syncthreads();
    float mu = mu_s, rstd = rstd_s;
    for (int i = threadIdx.x; i < 2048; i += 256) {
        int c = g * CPG + (i >> 8);
        float ga = gamma[c] * rstd;
        float be = beta[c] - mu * ga;
        float4 v = xb[i];
        v.x = v.x * ga + be; v.y = v.y * ga + be;
        v.z = v.z * ga + be; v.w = v.w * ga + be;
        hb[i] = v;
    }
}

// ---------------------------------------------------------------------------
// Raw-PTX tf32 channel GEMM: out[b,m,n] = sum_k W[m,k]*inp[b,k,n] (+bias,+resid)
// Block 128Mx128N, BK=32 double-buffered cp.async. 8 warps (2x4); each warp
// 64x32 via 4x4 m16n8k8 fragments. Operands as raw fp32 bits (no cvt).
// ---------------------------------------------------------------------------
#define G2_LDW 36
#define G2_LDB 136
#define G2_LDE 132
#define G2_WS  (128 * G2_LDW)    // 4608
#define G2_BS  (32 * G2_LDB)     // 4352
#define G2_FLOATS (2 * G2_WS + 2 * G2_BS)   // 17920 floats -> 71680 B

template<int MOUT, bool QKV_MODE>
__global__ void __launch_bounds__(256, 2)
gemm_ptx(const float* __restrict__ W, const float* __restrict__ bias,
         const float* __restrict__ resid, float* __restrict__ outp) {
    extern __shared__ float sm[];
    float* Wbuf = sm;
    float* Bbuf = sm + 2 * G2_WS;

    const float* inp = QKV_MODE ? g_h : g_att;
    float*       out = QKV_MODE ? g_qkv : outp;

    int n0 = blockIdx.x * 128;
    int m0 = blockIdx.y * 128;
    int b  = blockIdx.z;
    const float* ib = inp + (size_t)b * CH * NSP;

    int lane = threadIdx.x & 31, warp = threadIdx.x >> 5;
    int g = lane >> 2, t = lane & 3;
    int wm = (warp & 1) * 64;        // warp m-offset (4 tiles of 16)
    int wn = (warp >> 1) * 32;       // warp n-offset (4 tiles of 8)

    float acc[4][4][4];
    #pragma unroll
    for (int mt = 0; mt < 4; mt++)
        #pragma unroll
        for (int nt = 0; nt < 4; nt++)
            #pragma unroll
            for (int c = 0; c < 4; c++) acc[mt][nt][c] = 0.f;

    auto issue = [&](int ch) {
        float* ws = Wbuf + (ch & 1) * G2_WS;
        float* bs = Bbuf + (ch & 1) * G2_BS;
        int k0 = ch * 32;
        #pragma unroll
        for (int idx = threadIdx.x; idx < 1024; idx += 256) {
            int row = idx >> 3, k4 = (idx & 7) * 4;
            __pipeline_memcpy_async(ws + row * G2_LDW + k4,
                W + (size_t)(m0 + row) * CH + k0 + k4, 16);
        }
        #pragma unroll
        for (int idx = threadIdx.x; idx < 1024; idx += 256) {
            int row = idx >> 5, n4 = (idx & 31) * 4;
            __pipeline_memcpy_async(bs + row * G2_LDB + n4,
                ib + (size_t)(k0 + row) * NSP + n0 + n4, 16);
        }
        __pipeline_commit();
    };

    issue(0);
    for (int ch = 0; ch < 8; ch++) {
        float* ws = Wbuf + (ch & 1) * G2_WS;
        float* bs = Bbuf + (ch & 1) * G2_BS;
        __pipeline_wait_prior(0);
        __syncthreads();
        if (ch < 7) issue(ch + 1);
        #pragma unroll
        for (int k8 = 0; k8 < 4; k8++) {
            int kk = k8 * 8;
            uint32_t a[4][4];
            #pragma unroll
            for (int mt = 0; mt < 4; mt++) {
                const float* wr = ws + (wm + mt * 16) * G2_LDW + kk;
                a[mt][0] = __float_as_uint(wr[g * G2_LDW + t]);
                a[mt][1] = __float_as_uint(wr[(g + 8) * G2_LDW + t]);
                a[mt][2] = __float_as_uint(wr[g * G2_LDW + t + 4]);
                a[mt][3] = __float_as_uint(wr[(g + 8) * G2_LDW + t + 4]);
            }
            uint32_t bb[4][2];
            #pragma unroll
            for (int nt = 0; nt < 4; nt++) {
                const float* br = bs + kk * G2_LDB + wn + nt * 8 + g;
                bb[nt][0] = __float_as_uint(br[t * G2_LDB]);
                bb[nt][1] = __float_as_uint(br[(t + 4) * G2_LDB]);
            }
            #pragma unroll
            for (int mt = 0; mt < 4; mt++)
                #pragma unroll
                for (int nt = 0; nt < 4; nt++)
                    mma8(acc[mt][nt], a[mt][0], a[mt][1], a[mt][2], a[mt][3],
                         bb[nt][0], bb[nt][1]);
        }
        __syncthreads();
    }

    // Epilogue: stage 128x128 into smem, add bias/resid, coalesced store
    float* Ss = sm;   // 128 x G2_LDE = 16896 floats (fits in 17920)
    #pragma unroll
    for (int mt = 0; mt < 4; mt++) {
        int r0 = wm + mt * 16 + g;
        #pragma unroll
        for (int nt = 0; nt < 4; nt++) {
            int cc = wn + nt * 8 + 2 * t;
            *(float2*)(Ss + r0 * G2_LDE + cc)       = make_float2(acc[mt][nt][0], acc[mt][nt][1]);
            *(float2*)(Ss + (r0 + 8) * G2_LDE + cc) = make_float2(acc[mt][nt][2], acc[mt][nt][3]);
        }
    }
    __syncthreads();
    for (int idx = threadIdx.x; idx < 4096; idx += 256) {
        int row = idx >> 5, n4 = (idx & 31) * 4;
        int m = m0 + row;
        float4 v = *(float4*)(Ss + row * G2_LDE + n4);
        float bv = bias[m];
        v.x += bv; v.y += bv; v.z += bv; v.w += bv;
        if (!QKV_MODE) {
            float4 rr = *(const float4*)(resid + ((size_t)b * MOUT + m) * NSP + n0 + n4);
            v.x += rr.x; v.y += rr.y; v.z += rr.z; v.w += rr.w;
        }
        *(float4*)(out + ((size_t)b * MOUT + m) * NSP + n0 + n4) = v;
    }
}

// ---------------------------------------------------------------------------
// Register-resident flash attention, raw PTX mma.m16n8k8 tf32 (unchanged R7).
// ---------------------------------------------------------------------------
#define LDQ 136
#define LDP 72
#define LDV 68
#define QS_OFF 0
#define PS_OFF (64 * LDQ)
#define VS_OFF (PS_OFF + 128 * LDP)
#define AT2_FLOATS (VS_OFF + 64 * LDV)    // 22272 floats -> 89088 B

__global__ void __launch_bounds__(256)
attn_reg() {
    extern __shared__ float sm[];
    float* Qs = sm + QS_OFF;
    float* Ps = sm + PS_OFF;   // K tile lives here too (first 64 rows)
    float* Vs = sm + VS_OFF;

    int qt = blockIdx.x, hh = blockIdx.y, b = blockIdx.z;
    const float* qb = g_qkv + ((size_t)b * 3 * CH + hh * 3 * HD) * NSP;
    const float* kb = qb + (size_t)HD * NSP;
    const float* vb = qb + (size_t)2 * HD * NSP;
    int n0 = qt * 128;

    int lane = threadIdx.x & 31, warp = threadIdx.x >> 5;
    int g = lane >> 2, t = lane & 3;
    int iw = warp * 16;

    for (int idx = threadIdx.x; idx < 2048; idx += 256) {
        int dd = idx >> 5, i4 = (idx & 31) * 4;
        float4 v = *(const float4*)(qb + (size_t)dd * NSP + n0 + i4);
        v.x *= 0.125f; v.y *= 0.125f; v.z *= 0.125f; v.w *= 0.125f;
        *(float4*)(Qs + dd * LDQ + i4) = v;
    }

    float o[8][4];
    #pragma unroll
    for (int n = 0; n < 8; n++)
        #pragma unroll
        for (int c = 0; c < 4; c++) o[n][c] = 0.f;
    float m0 = -INFINITY, m1 = -INFINITY, l0 = 0.f, l1 = 0.f;

    for (int tile = 0; tile < 16; tile++) {
        int j0 = tile * 64;
        for (int idx = threadIdx.x; idx < 1024; idx += 256) {
            int dd = idx >> 4, j4 = (idx & 15) * 4;
            *(float4*)(Ps + dd * LDP + j4) = *(const float4*)(kb + (size_t)dd * NSP + j0 + j4);
            *(float4*)(Vs + dd * LDV + j4) = *(const float4*)(vb + (size_t)dd * NSP + j0 + j4);
        }
        __syncthreads();

        float s[8][4];
        #pragma unroll
        for (int n = 0; n < 8; n++)
            #pragma unroll
            for (int c = 0; c < 4; c++) s[n][c] = 0.f;
        #pragma unroll
        for (int k = 0; k < 8; k++) {
            int d0 = k * 8;
            uint32_t a0 = __float_as_uint(Qs[(d0 + t)     * LDQ + iw + g]);
            uint32_t a1 = __float_as_uint(Qs[(d0 + t)     * LDQ + iw + g + 8]);
            uint32_t a2 = __float_as_uint(Qs[(d0 + t + 4) * LDQ + iw + g]);
            uint32_t a3 = __float_as_uint(Qs[(d0 + t + 4) * LDQ + iw + g + 8]);
            #pragma unroll
            for (int n = 0; n < 8; n++) {
                uint32_t b0 = __float_as_uint(Ps[(d0 + t)     * LDP + n * 8 + g]);
                uint32_t b1 = __float_as_uint(Ps[(d0 + t + 4) * LDP + n * 8 + g]);
                mma8(s[n], a0, a1, a2, a3, b0, b1);
            }
        }

        float mx0 = -INFINITY, mx1 = -INFINITY;
        #pragma unroll
        for (int n = 0; n < 8; n++) {
            mx0 = fmaxf(mx0, fmaxf(s[n][0], s[n][1]));
            mx1 = fmaxf(mx1, fmaxf(s[n][2], s[n][3]));
        }
        mx0 = fmaxf(mx0, __shfl_xor_sync(0xffffffffu, mx0, 1));
        mx0 = fmaxf(mx0, __shfl_xor_sync(0xffffffffu, mx0, 2));
        mx1 = fmaxf(mx1, __shfl_xor_sync(0xffffffffu, mx1, 1));
        mx1 = fmaxf(mx1, __shfl_xor_sync(0xffffffffu, mx1, 2));
        float mn0 = fmaxf(m0, mx0), mn1 = fmaxf(m1, mx1);
        float al0 = __expf(m0 - mn0), al1 = __expf(m1 - mn1);
        m0 = mn0; m1 = mn1;
        float r0 = 0.f, r1 = 0.f;
        #pragma unroll
        for (int n = 0; n < 8; n++) {
            s[n][0] = __expf(s[n][0] - mn0);
            s[n][1] = __expf(s[n][1] - mn0);
            s[n][2] = __expf(s[n][2] - mn1);
            s[n][3] = __expf(s[n][3] - mn1);
            r0 += s[n][0] + s[n][1];
            r1 += s[n][2] + s[n][3];
        }
        r0 += __shfl_xor_sync(0xffffffffu, r0, 1);
        r0 += __shfl_xor_sync(0xffffffffu, r0, 2);
        r1 += __shfl_xor_sync(0xffffffffu, r1, 1);
        r1 += __shfl_xor_sync(0xffffffffu, r1, 2);
        l0 = l0 * al0 + r0;
        l1 = l1 * al1 + r1;
        #pragma unroll
        for (int n = 0; n < 8; n++) {
            o[n][0] *= al0; o[n][1] *= al0;
            o[n][2] *= al1; o[n][3] *= al1;
        }
        __syncthreads();

        #pragma unroll
        for (int n = 0; n < 8; n++) {
            *(float2*)(Ps + (iw + g)     * LDP + n * 8 + 2 * t) = make_float2(s[n][0], s[n][1]);
            *(float2*)(Ps + (iw + g + 8) * LDP + n * 8 + 2 * t) = make_float2(s[n][2], s[n][3]);
        }
        __syncthreads();

        #pragma unroll
        for (int j = 0; j < 8; j++) {
            int jj = j * 8;
            uint32_t a0 = __float_as_uint(Ps[(iw + g)     * LDP + jj + t]);
            uint32_t a1 = __float_as_uint(Ps[(iw + g + 8) * LDP + jj + t]);
            uint32_t a2 = __float_as_uint(Ps[(iw + g)     * LDP + jj + t + 4]);
            uint32_t a3 = __float_as_uint(Ps[(iw + g + 8) * LDP + jj + t + 4]);
            #pragma unroll
            for (int n = 0; n < 8; n++) {
                uint32_t b0 = __float_as_uint(Vs[(n * 8 + g) * LDV + jj + t]);
                uint32_t b1 = __float_as_uint(Vs[(n * 8 + g) * LDV + jj + t + 4]);
                mma8(o[n], a0, a1, a2, a3, b0, b1);
            }
        }
        __syncthreads();
    }

    float inv0 = 1.f / l0, inv1 = 1.f / l1;
    #pragma unroll
    for (int n = 0; n < 8; n++) {
        o[n][0] *= inv0; o[n][1] *= inv0;
        o[n][2] *= inv1; o[n][3] *= inv1;
    }
    float* Os = Ps;
    #pragma unroll
    for (int n = 0; n < 8; n++) {
        int dc = n * 8 + 2 * t;
        Os[dc * 132 + iw + g]           = o[n][0];
        Os[(dc + 1) * 132 + iw + g]     = o[n][1];
        Os[dc * 132 + iw + g + 8]       = o[n][2];
        Os[(dc + 1) * 132 + iw + g + 8] = o[n][3];
    }
    __syncthreads();
    float* ob = g_att + ((size_t)b * CH + hh * HD) * NSP + n0;
    for (int idx = threadIdx.x; idx < 2048; idx += 256) {
        int dc = idx >> 5, i4 = (idx & 31) * 4;
        *(float4*)(ob + (size_t)dc * NSP + i4) = *(float4*)(Os + dc * 132 + i4);
    }
}

// ---------------------------------------------------------------------------

extern "C" void kernel_launch(void* const* d_in, const int* in_sizes, int n_in,
                              void* d_out, int out_size) {
    const float* x      = (const float*)d_in[0];
    const float* gamma  = (const float*)d_in[1];
    const float* beta   = (const float*)d_in[2];
    const float* qkv_w  = (const float*)d_in[3];
    const float* qkv_b  = (const float*)d_in[4];
    const float* proj_w = (const float*)d_in[5];
    const float* proj_b = (const float*)d_in[6];
    float* out = (float*)d_out;

    const int gm_smem  = G2_FLOATS * 4;
    const int att_smem = AT2_FLOATS * 4;

    cudaFuncSetAttribute(gemm_ptx<768, true>,
                         cudaFuncAttributeMaxDynamicSharedMemorySize, gm_smem);
    cudaFuncSetAttribute(gemm_ptx<256, false>,
                         cudaFuncAttributeMaxDynamicSharedMemorySize, gm_smem);
    cudaFuncSetAttribute(attn_reg,
                         cudaFuncAttributeMaxDynamicSharedMemorySize, att_smem);

    gn_kernel<<<BATCH * NGRP, 256>>>(x, gamma, beta);
    gemm_ptx<768, true ><<<dim3(8, 6, BATCH), 256, gm_smem>>>(qkv_w, qkv_b, 0, 0);
    attn_reg<<<dim3(NSP / 128, NHEADS, BATCH), 256, att_smem>>>();
    gemm_ptx<256, false><<<dim3(8, 2, BATCH), 256, gm_smem>>>(proj_w, proj_b, x, out);
}